// round 8
// baseline (speedup 1.0000x reference)
#include <cuda_runtime.h>
#include <math.h>
#include <stdint.h>

#define BB   64
#define SS   512
#define EE   128
#define HH   256
#define G4   1024
#define E2   512
#define NHH  4
#define HD   128
#define LL   9
#define NTOK (BB*SS)

// ---------------- scratch ------------------------------------------------------
__device__ float  g_xg[(size_t)2*SS*G4*BB];    // [d][t][g][b]
__device__ float  g_h[2*2*HH*BB];              // [buf][d][unit][b]
__device__ float  g_c[2*HH*BB];                // [d][unit][b]
__device__ float4 g_wpack[2*HH*HH];            // [d][unit][k] -> (wi,wf,wg,wo)
__device__ float  g_hall[(size_t)NTOK*E2];     // [token=b*S+t][512]
__device__ float  g_qkv[(size_t)NTOK*3*E2];
__device__ float  g_att[(size_t)NTOK*E2];
__device__ float  g_ao[(size_t)NTOK*E2];
__device__ float  g_em[(size_t)NTOK*LL];

#define PROJ_SMEM ((128*132 + 64*129)*4)
#define STEP_SMEM (16384*4)
#define ATTN_SMEM ((64*129*2 + 64*65)*4)

__device__ __forceinline__ float sigf(float x) { return 1.f / (1.f + expf(-x)); }

// ---------------- reset --------------------------------------------------------
__global__ void reset_kernel() {
    int idx = blockIdx.x * blockDim.x + threadIdx.x;
    if (idx < 2*2*HH*BB) g_h[idx] = 0.f;
    if (idx < 2*HH*BB)   g_c[idx] = 0.f;
}

// ---------------- pack recurrent weights: [d][unit][k] float4 over gates -------
__global__ void pack_kernel(const float* __restrict__ whh_f,
                            const float* __restrict__ whh_b) {
    int idx = blockIdx.x * blockDim.x + threadIdx.x;   // 0 .. 2*256*256-1
    int k = idx & 255;
    int u = (idx >> 8) & 255;
    int d = idx >> 16;
    const float* w = d ? whh_b : whh_f;
    g_wpack[idx] = make_float4(w[(size_t)u * HH + k],
                               w[(size_t)(256 + u) * HH + k],
                               w[(size_t)(512 + u) * HH + k],
                               w[(size_t)(768 + u) * HH + k]);
}

// ---------------- fused embed + input projection -------------------------------
// xg[d][t][g][b] = b_d[g] + sum_e embed[input[b][t]][e] * w_ih_d[g][e]
__global__ void __launch_bounds__(256) proj_kernel(
    const int* __restrict__ inp, const float* __restrict__ embed,
    const float* __restrict__ w_f, const float* __restrict__ b_f,
    const float* __restrict__ w_b, const float* __restrict__ b_b)
{
    int t  = blockIdx.x;
    int gt = blockIdx.y;                 // 16 tiles of 128 rows over 2048 (2 dirs)
    extern __shared__ float sm_p[];
    float* Ws = sm_p;                    // [128][132]
    float* Xs = sm_p + 128*132;          // [64][129]
    __shared__ int rows_s[BB];

    int tid = threadIdx.x;
    int r0 = gt * 128;
    int d  = (r0 >= G4) ? 1 : 0;
    const float* w    = d ? w_b : w_f;
    const float* bias = d ? b_b : b_f;
    int rloc0 = r0 - d * G4;

    if (tid < BB) rows_s[tid] = inp[tid * SS + t];
    __syncthreads();

    #pragma unroll
    for (int i = 0; i < 16; i++) {
        int idx4 = tid + 256 * i;        // 4096 float4 of W
        int g  = idx4 >> 5;
        int kq = idx4 & 31;
        float4 v = *(const float4*)(w + (size_t)(rloc0 + g) * EE + kq * 4);
        *(float4*)&Ws[g * 132 + kq * 4] = v;
    }
    #pragma unroll
    for (int i = 0; i < 8; i++) {
        int idx4 = tid + 256 * i;        // 2048 float4 of X
        int b  = idx4 >> 5;
        int eq = idx4 & 31;
        float4 v = *(const float4*)(embed + (size_t)rows_s[b] * EE + eq * 4);
        Xs[b*129 + eq*4+0] = v.x; Xs[b*129 + eq*4+1] = v.y;
        Xs[b*129 + eq*4+2] = v.z; Xs[b*129 + eq*4+3] = v.w;
    }
    __syncthreads();

    int tx = tid & 15, ty = tid >> 4;
    float acc[8][4];
    #pragma unroll
    for (int i = 0; i < 8; i++)
        #pragma unroll
        for (int j = 0; j < 4; j++) acc[i][j] = 0.f;

    #pragma unroll 4
    for (int k = 0; k < EE; k++) {
        float xv[4];
        #pragma unroll
        for (int q = 0; q < 4; q++) xv[q] = Xs[(tx + 16*q) * 129 + k];
        #pragma unroll
        for (int i = 0; i < 8; i++) {
            float wv = Ws[(ty * 8 + i) * 132 + k];
            #pragma unroll
            for (int q = 0; q < 4; q++) acc[i][q] += wv * xv[q];
        }
    }

    #pragma unroll
    for (int i = 0; i < 8; i++) {
        int grow = rloc0 + ty * 8 + i;
        float bv = bias[grow];
        size_t base = ((size_t)(d * SS + t) * G4 + grow) * BB;
        #pragma unroll
        for (int q = 0; q < 4; q++)
            g_xg[base + tx + 16*q] = acc[i][q] + bv;
    }
}

// ---------------- one BiLSTM time step (both directions) -----------------------
// grid = 128 CTAs: cta 0-63 forward, 64-127 backward; each owns 4 units x 64 b.
// Inter-step coherence comes from the kernel boundary; no grid barrier.
__global__ void __launch_bounds__(256) lstm_step_kernel(int t)
{
    int cta = blockIdx.x & 63;
    int d   = blockIdx.x >> 6;

    extern __shared__ float Hs[];        // [256 k][64 b]
    int tid = threadIdx.x;
    int ul = tid >> 6, b = tid & 63;
    int u  = cta * 4 + ul;

    int tt = d ? (SS - 1 - t) : t;
    int rbuf = t & 1;

    // stage h_prev slab into smem (coalesced float4)
    const float4* src = (const float4*)(g_h + (size_t)(rbuf * 2 + d) * HH * BB);
    float4* dst = (float4*)Hs;
    #pragma unroll
    for (int i = 0; i < 16; i++)
        dst[tid + 256 * i] = src[tid + 256 * i];

    size_t base = (size_t)(d * SS + tt) * G4 * BB;
    float4 acc;
    acc.x = g_xg[base + (size_t)(u      ) * BB + b];
    acc.y = g_xg[base + (size_t)(256 + u) * BB + b];
    acc.z = g_xg[base + (size_t)(512 + u) * BB + b];
    acc.w = g_xg[base + (size_t)(768 + u) * BB + b];
    float c = g_c[((size_t)d * HH + u) * BB + b];
    __syncthreads();

    // warp-uniform weight rows: all 32 lanes of a warp share ul -> broadcast LDG
    const float4* wrow = g_wpack + ((size_t)d * HH + u) * HH;
    #pragma unroll 8
    for (int k = 0; k < HH; k++) {
        float hv = Hs[k * 64 + b];
        float4 wv = wrow[k];
        acc.x += wv.x * hv;
        acc.y += wv.y * hv;
        acc.z += wv.z * hv;
        acc.w += wv.w * hv;
    }

    float ig = sigf(acc.x);
    float fg = sigf(acc.y);
    float gg = tanhf(acc.z);
    float og = sigf(acc.w);
    c = fg * c + ig * gg;
    float hval = og * tanhf(c);

    g_c[((size_t)d * HH + u) * BB + b] = c;
    int wbuf = rbuf ^ 1;
    g_h[((size_t)(wbuf * 2 + d) * HH + u) * BB + b] = hval;
    g_hall[(size_t)(b * SS + tt) * E2 + d * HH + u] = hval;
}

// ---------------- SGEMM: C[M,N] = A[M,K] @ W[N,K]^T + bias ---------------------
__global__ void __launch_bounds__(256) sgemm_bias(
    const float* __restrict__ A, const float* __restrict__ W,
    const float* __restrict__ bias, float* __restrict__ C,
    int M, int N, int K)
{
    __shared__ float As[16][132];
    __shared__ float Bs[16][132];
    int tid = threadIdx.x;
    int bn = blockIdx.x * 128, bm = blockIdx.y * 128;
    int tx = tid & 15, ty = tid >> 4;

    float acc[8][8];
    #pragma unroll
    for (int i = 0; i < 8; i++)
        #pragma unroll
        for (int j = 0; j < 8; j++) acc[i][j] = 0.f;

    for (int k0 = 0; k0 < K; k0 += 16) {
        #pragma unroll
        for (int i = 0; i < 2; i++) {
            int idx4 = tid + 256 * i;        // 512 float4: 128 rows x 4
            int row = idx4 >> 2;
            int kq  = idx4 & 3;
            float4 va = *(const float4*)(A + (size_t)(bm + row) * K + k0 + kq * 4);
            As[kq*4+0][row] = va.x; As[kq*4+1][row] = va.y;
            As[kq*4+2][row] = va.z; As[kq*4+3][row] = va.w;
            float4 vb = *(const float4*)(W + (size_t)(bn + row) * K + k0 + kq * 4);
            Bs[kq*4+0][row] = vb.x; Bs[kq*4+1][row] = vb.y;
            Bs[kq*4+2][row] = vb.z; Bs[kq*4+3][row] = vb.w;
        }
        __syncthreads();
        #pragma unroll
        for (int k = 0; k < 16; k++) {
            float a[8], br[8];
            *(float4*)&a[0]  = *(float4*)&As[k][ty * 8];
            *(float4*)&a[4]  = *(float4*)&As[k][ty * 8 + 4];
            *(float4*)&br[0] = *(float4*)&Bs[k][tx * 8];
            *(float4*)&br[4] = *(float4*)&Bs[k][tx * 8 + 4];
            #pragma unroll
            for (int i = 0; i < 8; i++)
                #pragma unroll
                for (int j = 0; j < 8; j++) acc[i][j] += a[i] * br[j];
        }
        __syncthreads();
    }

    #pragma unroll
    for (int i = 0; i < 8; i++) {
        int r = bm + ty * 8 + i;
        #pragma unroll
        for (int j = 0; j < 8; j++) {
            int cn = bn + tx * 8 + j;
            C[(size_t)r * N + cn] = acc[i][j] + bias[cn];
        }
    }
}

// ---------------- batch-axis attention: per (s, head) 64x64 --------------------
__global__ void __launch_bounds__(256) attn_kernel()
{
    int s = blockIdx.x, h = blockIdx.y;
    extern __shared__ float sm_a[];
    float* Qs = sm_a;                    // [64][129] (reused for V)
    float* Ks = sm_a + 64 * 129;
    float* Ss = sm_a + 2 * 64 * 129;     // [64][65]
    int tid = threadIdx.x;

    #pragma unroll
    for (int i = 0; i < 8; i++) {
        int idx4 = tid + 256 * i;        // 2048 float4 per matrix
        int b  = idx4 >> 5;
        int dq = idx4 & 31;
        size_t rbase = (size_t)(b * SS + s) * (3 * E2) + h * HD + dq * 4;
        float4 q = *(const float4*)(g_qkv + rbase);
        float4 k = *(const float4*)(g_qkv + rbase + E2);
        Qs[b*129 + dq*4+0] = q.x; Qs[b*129 + dq*4+1] = q.y;
        Qs[b*129 + dq*4+2] = q.z; Qs[b*129 + dq*4+3] = q.w;
        Ks[b*129 + dq*4+0] = k.x; Ks[b*129 + dq*4+1] = k.y;
        Ks[b*129 + dq*4+2] = k.z; Ks[b*129 + dq*4+3] = k.w;
    }
    __syncthreads();

    const float scale = 0.08838834764831845f;   // 1/sqrt(128)
    #pragma unroll
    for (int e0 = 0; e0 < 16; e0++) {
        int e = tid + 256 * e0;          // 4096 scores
        int i = e >> 6, j = e & 63;
        float acc = 0.f;
        #pragma unroll 4
        for (int k = 0; k < HD; k++) acc += Qs[i*129 + k] * Ks[j*129 + k];
        Ss[i * 65 + j] = acc * scale;
    }
    __syncthreads();

    // V into Qs (Q dead after scores)
    #pragma unroll
    for (int i = 0; i < 8; i++) {
        int idx4 = tid + 256 * i;
        int b  = idx4 >> 5;
        int dq = idx4 & 31;
        size_t rbase = (size_t)(b * SS + s) * (3 * E2) + h * HD + dq * 4 + 2 * E2;
        float4 v = *(const float4*)(g_qkv + rbase);
        Qs[b*129 + dq*4+0] = v.x; Qs[b*129 + dq*4+1] = v.y;
        Qs[b*129 + dq*4+2] = v.z; Qs[b*129 + dq*4+3] = v.w;
    }
    __syncthreads();
    if (tid < 64) {
        int i = tid;
        float m = -1e30f;
        #pragma unroll 4
        for (int j = 0; j < 64; j++) m = fmaxf(m, Ss[i*65 + j]);
        float sum = 0.f;
        #pragma unroll 4
        for (int j = 0; j < 64; j++) {
            float ev = expf(Ss[i*65 + j] - m);
            Ss[i*65 + j] = ev;
            sum += ev;
        }
        float inv = 1.f / sum;
        #pragma unroll 4
        for (int j = 0; j < 64; j++) Ss[i*65 + j] *= inv;
    }
    __syncthreads();

    #pragma unroll
    for (int o0 = 0; o0 < 32; o0++) {
        int idx = tid + 256 * o0;        // 8192 outputs
        int i = idx >> 7, dd = idx & 127;
        float acc = 0.f;
        #pragma unroll 4
        for (int j = 0; j < 64; j++) acc += Ss[i*65 + j] * Qs[j*129 + dd];
        g_att[(size_t)(i * SS + s) * E2 + h * HD + dd] = acc;
    }
}

// ---------------- emissions: em = ao @ w_lin^T + b_lin -------------------------
__global__ void __launch_bounds__(256) em_kernel(
    const float* __restrict__ wl, const float* __restrict__ bl)
{
    __shared__ float ws[LL * E2];
    __shared__ float bs[LL];
    int tid = threadIdx.x;
    for (int i = tid; i < LL * E2; i += 256) ws[i] = wl[i];
    if (tid < LL) bs[tid] = bl[tid];
    __syncthreads();

    int warp = tid >> 5, lane = tid & 31;
    int token = blockIdx.x * 8 + warp;

    const float* arow = g_ao + (size_t)token * E2;
    float acc[LL];
    #pragma unroll
    for (int j = 0; j < LL; j++) acc[j] = 0.f;

    #pragma unroll 4
    for (int it = 0; it < E2 / 32; it++) {
        int dd = lane + 32 * it;
        float a = arow[dd];
        #pragma unroll
        for (int j = 0; j < LL; j++) acc[j] += a * ws[j * E2 + dd];
    }
    #pragma unroll
    for (int j = 0; j < LL; j++) {
        float v = acc[j];
        #pragma unroll
        for (int off = 16; off; off >>= 1)
            v += __shfl_down_sync(0xffffffffu, v, off);
        if (lane == 0) g_em[(size_t)token * LL + j] = v + bs[j];
    }
}

// ---------------- Viterbi decode: one warp per batch ---------------------------
// NOTE: output written as FLOAT32 (metadata __output__ dtype), not int32.
__global__ void __launch_bounds__(32) viterbi_kernel(
    const float* __restrict__ start, const float* __restrict__ endv,
    const float* __restrict__ trans, float* __restrict__ out)
{
    int b = blockIdx.x;
    int j = threadIdx.x;
    __shared__ unsigned char hist[SS * LL];

    const float* em = g_em + (size_t)b * SS * LL;

    float tr[LL];
    if (j < LL) {
        #pragma unroll
        for (int i = 0; i < LL; i++) tr[i] = trans[i * LL + j];
    }
    float score = (j < LL) ? (start[j] + em[j]) : -1e30f;

    for (int t = 1; t < SS; t++) {
        float e = (j < LL) ? em[t * LL + j] : 0.f;
        float best = -1e30f;
        int bi = 0;
        #pragma unroll
        for (int i = 0; i < LL; i++) {
            float si = __shfl_sync(0xffffffffu, score, i);
            float v = si + ((j < LL) ? tr[i] : 0.f);
            if (v > best) { best = v; bi = i; }
        }
        if (j < LL) hist[t * LL + j] = (unsigned char)bi;
        score = best + e;
    }
    if (j < LL) score += endv[j];

    // convergence-safe final argmax (first-max tie-break == jnp.argmax):
    // all 32 lanes execute an identical shfl sequence.
    float s = (j < LL) ? score : -3e30f;
    int   idx = j;
    #pragma unroll
    for (int off = 16; off; off >>= 1) {
        float so = __shfl_down_sync(0xffffffffu, s, off);
        int   io = __shfl_down_sync(0xffffffffu, idx, off);
        if (so > s || (so == s && io < idx)) { s = so; idx = io; }
    }
    int last = __shfl_sync(0xffffffffu, idx, 0);

    __syncwarp();
    if (j == 0) {
        out[b * SS + SS - 1] = (float)last;
        int tag = last;
        for (int t = SS - 1; t >= 1; t--) {
            tag = hist[t * LL + tag];
            out[b * SS + t - 1] = (float)tag;
        }
    }
}

// ---------------- launch -------------------------------------------------------
extern "C" void kernel_launch(void* const* d_in, const int* in_sizes, int n_in,
                              void* d_out, int out_size)
{
    // ---- size-based input dispatch (robust to pruned metadata) ----
    const void *p_input=0, *p_embed=0, *p_wihf=0, *p_bf=0, *p_wihb=0, *p_bb=0;
    const void *p_whhf=0, *p_whhb=0, *p_wo=0, *p_wqkv=0, *p_bqkv=0, *p_bo=0;
    const void *p_wlin=0, *p_blin=0, *p_start=0, *p_end=0, *p_trans=0;
    int c32k = 0, c131k = 0, c262k = 0, c1k = 0, c9 = 0;
    for (int i = 0; i < n_in; i++) {
        int sz = in_sizes[i];
        const void* p = d_in[i];
        if      (sz == 252160) p_embed = p;
        else if (sz == 786432) p_wqkv  = p;
        else if (sz == 1536)   p_bqkv  = p;
        else if (sz == 512)    p_bo    = p;
        else if (sz == 4608)   p_wlin  = p;
        else if (sz == 81)     p_trans = p;
        else if (sz == 32768)  { if (c32k == 0) p_input = p; c32k++; }
        else if (sz == 131072) { if (c131k == 0) p_wihf = p; else p_wihb = p; c131k++; }
        else if (sz == 262144) { if (c262k == 0) p_whhf = p; else if (c262k == 1) p_whhb = p; else p_wo = p; c262k++; }
        else if (sz == 1024)   { if (c1k == 0) p_bf = p; else p_bb = p; c1k++; }
        else if (sz == 9)      { if (c9 == 0) p_blin = p; else if (c9 == 1) p_start = p; else p_end = p; c9++; }
    }

    const int*   inp    = (const int*)  p_input;
    const float* embed  = (const float*)p_embed;
    const float* w_ih_f = (const float*)p_wihf;
    const float* w_hh_f = (const float*)p_whhf;
    const float* b_f    = (const float*)p_bf;
    const float* w_ih_b = (const float*)p_wihb;
    const float* w_hh_b = (const float*)p_whhb;
    const float* b_b    = (const float*)p_bb;
    const float* wqkv   = (const float*)p_wqkv;
    const float* bqkv   = (const float*)p_bqkv;
    const float* wo     = (const float*)p_wo;
    const float* bo     = (const float*)p_bo;
    const float* w_lin  = (const float*)p_wlin;
    const float* b_lin  = (const float*)p_blin;
    const float* startv = (const float*)p_start;
    const float* endv   = (const float*)p_end;
    const float* transv = (const float*)p_trans;
    float* out = (float*)d_out;

    cudaFuncSetAttribute(proj_kernel,      cudaFuncAttributeMaxDynamicSharedMemorySize, PROJ_SMEM);
    cudaFuncSetAttribute(lstm_step_kernel, cudaFuncAttributeMaxDynamicSharedMemorySize, STEP_SMEM);
    cudaFuncSetAttribute(attn_kernel,      cudaFuncAttributeMaxDynamicSharedMemorySize, ATTN_SMEM);

    float* g_hall_p; cudaGetSymbolAddress((void**)&g_hall_p, g_hall);
    float* g_qkv_p;  cudaGetSymbolAddress((void**)&g_qkv_p,  g_qkv);
    float* g_att_p;  cudaGetSymbolAddress((void**)&g_att_p,  g_att);
    float* g_ao_p;   cudaGetSymbolAddress((void**)&g_ao_p,   g_ao);

    reset_kernel<<<256, 256>>>();
    pack_kernel<<<512, 256>>>(w_hh_f, w_hh_b);
    proj_kernel<<<dim3(SS, 16), 256, PROJ_SMEM>>>(inp, embed, w_ih_f, b_f, w_ih_b, b_b);
    for (int t = 0; t < SS; t++)
        lstm_step_kernel<<<128, 256, STEP_SMEM>>>(t);
    sgemm_bias<<<dim3(12, 256), 256>>>(g_hall_p, wqkv, bqkv, g_qkv_p, NTOK, 3*E2, E2);
    attn_kernel<<<dim3(SS, NHH), 256, ATTN_SMEM>>>();
    sgemm_bias<<<dim3(4, 256), 256>>>(g_att_p, wo, bo, g_ao_p, NTOK, E2, E2);
    em_kernel<<<NTOK/8, 256>>>(w_lin, b_lin);
    viterbi_kernel<<<BB, 32>>>(startv, endv, transv, out);
}

// round 9
// speedup vs baseline: 2.1750x; 2.1750x over previous
#include <cuda_runtime.h>
#include <math.h>
#include <stdint.h>

#define BB   64
#define SS   512
#define EE   128
#define HH   256
#define G4   1024
#define E2   512
#define NHH  4
#define HD   128
#define LL   9
#define NTOK (BB*SS)

// ---------------- scratch ------------------------------------------------------
__device__ float  g_xg[(size_t)2*SS*G4*BB];    // [d][t][g][b]
__device__ float  g_h[2*2*HH*BB];              // [buf][d][unit][b]
__device__ float  g_hall[(size_t)NTOK*E2];     // [token=b*S+t][512]
__device__ float  g_qkv[(size_t)NTOK*3*E2];
__device__ float  g_att[(size_t)NTOK*E2];
__device__ float  g_ao[(size_t)NTOK*E2];
__device__ float  g_em[(size_t)NTOK*LL];
__device__ unsigned int g_bar;

#define PROJ_SMEM ((128*132 + 64*129)*4)
#define LSTM_SMEM ((1024*4 + 16384)*4)
#define ATTN_SMEM ((64*129*2 + 64*65)*4)

__device__ __forceinline__ float sigf(float x) { return 1.f / (1.f + expf(-x)); }

// ---------------- reset --------------------------------------------------------
__global__ void reset_kernel() {
    int idx = blockIdx.x * blockDim.x + threadIdx.x;
    if (idx < 2*2*HH*BB) g_h[idx] = 0.f;
    if (idx == 0) g_bar = 0u;
}

// ---------------- fused embed + input projection -------------------------------
// xg[d][t][g][b] = b_d[g] + sum_e embed[input[b][t]][e] * w_ih_d[g][e]
__global__ void __launch_bounds__(256) proj_kernel(
    const int* __restrict__ inp, const float* __restrict__ embed,
    const float* __restrict__ w_f, const float* __restrict__ b_f,
    const float* __restrict__ w_b, const float* __restrict__ b_b)
{
    int t  = blockIdx.x;
    int gt = blockIdx.y;                 // 16 tiles of 128 rows over 2048 (2 dirs)
    extern __shared__ float sm_p[];
    float* Ws = sm_p;                    // [128][132]
    float* Xs = sm_p + 128*132;          // [64][129]
    __shared__ int rows_s[BB];

    int tid = threadIdx.x;
    int r0 = gt * 128;
    int d  = (r0 >= G4) ? 1 : 0;
    const float* w    = d ? w_b : w_f;
    const float* bias = d ? b_b : b_f;
    int rloc0 = r0 - d * G4;

    if (tid < BB) rows_s[tid] = inp[tid * SS + t];
    __syncthreads();

    #pragma unroll
    for (int i = 0; i < 16; i++) {
        int idx4 = tid + 256 * i;        // 4096 float4 of W
        int g  = idx4 >> 5;
        int kq = idx4 & 31;
        float4 v = *(const float4*)(w + (size_t)(rloc0 + g) * EE + kq * 4);
        *(float4*)&Ws[g * 132 + kq * 4] = v;
    }
    #pragma unroll
    for (int i = 0; i < 8; i++) {
        int idx4 = tid + 256 * i;        // 2048 float4 of X
        int b  = idx4 >> 5;
        int eq = idx4 & 31;
        float4 v = *(const float4*)(embed + (size_t)rows_s[b] * EE + eq * 4);
        Xs[b*129 + eq*4+0] = v.x; Xs[b*129 + eq*4+1] = v.y;
        Xs[b*129 + eq*4+2] = v.z; Xs[b*129 + eq*4+3] = v.w;
    }
    __syncthreads();

    int tx = tid & 15, ty = tid >> 4;
    float acc[8][4];
    #pragma unroll
    for (int i = 0; i < 8; i++)
        #pragma unroll
        for (int j = 0; j < 4; j++) acc[i][j] = 0.f;

    #pragma unroll 4
    for (int k = 0; k < EE; k++) {
        float xv[4];
        #pragma unroll
        for (int q = 0; q < 4; q++) xv[q] = Xs[(tx + 16*q) * 129 + k];
        #pragma unroll
        for (int i = 0; i < 8; i++) {
            float wv = Ws[(ty * 8 + i) * 132 + k];
            #pragma unroll
            for (int q = 0; q < 4; q++) acc[i][q] += wv * xv[q];
        }
    }

    #pragma unroll
    for (int i = 0; i < 8; i++) {
        int grow = rloc0 + ty * 8 + i;
        float bv = bias[grow];
        size_t base = ((size_t)(d * SS + t) * G4 + grow) * BB;
        #pragma unroll
        for (int q = 0; q < 4; q++)
            g_xg[base + tx + 16*q] = acc[i][q] + bv;
    }
}

// ---------------- persistent BiLSTM with release/acquire grid barrier ----------
// 128 CTAs (<=148 SMs, 1 CTA/SM by smem) -> full wave-1 co-residency guaranteed.
__global__ void __launch_bounds__(256,1) lstm_kernel(
    const float* __restrict__ whh_f, const float* __restrict__ whh_b)
{
    int cta = blockIdx.x & 63;
    int d   = blockIdx.x >> 6;
    const float* w = d ? whh_b : whh_f;

    extern __shared__ float sm_l[];
    float4* Wg = (float4*)sm_l;          // [4 units][256 k] -> (wi,wf,wg,wo)
    float*  Hs = sm_l + 4096;            // [256 k][64 b]

    int tid = threadIdx.x;
    int ul = tid >> 6, b = tid & 63;
    int u  = cta * 4 + ul;

    for (int i = tid; i < 1024; i += 256) {
        int uu = i >> 8, k = i & 255;
        int ug = cta * 4 + uu;
        Wg[i] = make_float4(w[(size_t)ug * HH + k],
                            w[(size_t)(256 + ug) * HH + k],
                            w[(size_t)(512 + ug) * HH + k],
                            w[(size_t)(768 + ug) * HH + k]);
    }

    float c = 0.f;
    unsigned nCTA = gridDim.x;
    unsigned int* barp = &g_bar;

    for (int t = 0; t < SS; t++) {
        int tt = d ? (SS - 1 - t) : t;
        int rbuf = t & 1;

        // stage h_prev (all 256 units x 64 batches) into smem, L1-bypassed
        const float4* src = (const float4*)(g_h + (size_t)(rbuf * 2 + d) * HH * BB);
        float4* dst = (float4*)Hs;
        #pragma unroll
        for (int i = 0; i < 16; i++)
            dst[tid + 256 * i] = __ldcg(src + tid + 256 * i);

        size_t base = (size_t)(d * SS + tt) * G4 * BB;
        float4 acc;
        acc.x = g_xg[base + (size_t)(u      ) * BB + b];
        acc.y = g_xg[base + (size_t)(256 + u) * BB + b];
        acc.z = g_xg[base + (size_t)(512 + u) * BB + b];
        acc.w = g_xg[base + (size_t)(768 + u) * BB + b];
        __syncthreads();

        const float4* wrow = Wg + ul * 256;
        #pragma unroll 8
        for (int k = 0; k < HH; k++) {
            float hv = Hs[k * 64 + b];
            float4 wv = wrow[k];
            acc.x += wv.x * hv;
            acc.y += wv.y * hv;
            acc.z += wv.z * hv;
            acc.w += wv.w * hv;
        }

        float ig = sigf(acc.x);
        float fg = sigf(acc.y);
        float gg = tanhf(acc.z);
        float og = sigf(acc.w);
        c = fg * c + ig * gg;
        float hval = og * tanhf(c);

        int wbuf = rbuf ^ 1;
        __stcg(&g_h[((size_t)(wbuf * 2 + d) * HH + u) * BB + b], hval);
        g_hall[(size_t)(b * SS + tt) * E2 + d * HH + u] = hval;

        // ---- grid barrier: release arrive, acquire spin (coop-groups pattern)
        __threadfence();                 // make h stores GPU-visible pre-arrive
        __syncthreads();                 // all CTA threads' stores done
        if (tid == 0) {
            asm volatile("red.release.gpu.global.add.u32 [%0], %1;"
                         :: "l"(barp), "r"(1u) : "memory");
            unsigned target = nCTA * (unsigned)(t + 1);
            unsigned v;
            do {
                asm volatile("ld.acquire.gpu.global.u32 %0, [%1];"
                             : "=r"(v) : "l"(barp) : "memory");
                if (v >= target) break;
                __nanosleep(64);
            } while (1);
        }
        __syncthreads();                 // propagate acquire to whole CTA
    }
}

// ---------------- SGEMM: C[M,N] = A[M,K] @ W[N,K]^T + bias ---------------------
__global__ void __launch_bounds__(256) sgemm_bias(
    const float* __restrict__ A, const float* __restrict__ W,
    const float* __restrict__ bias, float* __restrict__ C,
    int M, int N, int K)
{
    __shared__ float As[16][132];
    __shared__ float Bs[16][132];
    int tid = threadIdx.x;
    int bn = blockIdx.x * 128, bm = blockIdx.y * 128;
    int tx = tid & 15, ty = tid >> 4;

    float acc[8][8];
    #pragma unroll
    for (int i = 0; i < 8; i++)
        #pragma unroll
        for (int j = 0; j < 8; j++) acc[i][j] = 0.f;

    for (int k0 = 0; k0 < K; k0 += 16) {
        #pragma unroll
        for (int i = 0; i < 2; i++) {
            int idx4 = tid + 256 * i;        // 512 float4: 128 rows x 4
            int row = idx4 >> 2;
            int kq  = idx4 & 3;
            float4 va = *(const float4*)(A + (size_t)(bm + row) * K + k0 + kq * 4);
            As[kq*4+0][row] = va.x; As[kq*4+1][row] = va.y;
            As[kq*4+2][row] = va.z; As[kq*4+3][row] = va.w;
            float4 vb = *(const float4*)(W + (size_t)(bn + row) * K + k0 + kq * 4);
            Bs[kq*4+0][row] = vb.x; Bs[kq*4+1][row] = vb.y;
            Bs[kq*4+2][row] = vb.z; Bs[kq*4+3][row] = vb.w;
        }
        __syncthreads();
        #pragma unroll
        for (int k = 0; k < 16; k++) {
            float a[8], br[8];
            *(float4*)&a[0]  = *(float4*)&As[k][ty * 8];
            *(float4*)&a[4]  = *(float4*)&As[k][ty * 8 + 4];
            *(float4*)&br[0] = *(float4*)&Bs[k][tx * 8];
            *(float4*)&br[4] = *(float4*)&Bs[k][tx * 8 + 4];
            #pragma unroll
            for (int i = 0; i < 8; i++)
                #pragma unroll
                for (int j = 0; j < 8; j++) acc[i][j] += a[i] * br[j];
        }
        __syncthreads();
    }

    #pragma unroll
    for (int i = 0; i < 8; i++) {
        int r = bm + ty * 8 + i;
        #pragma unroll
        for (int j = 0; j < 8; j++) {
            int cn = bn + tx * 8 + j;
            C[(size_t)r * N + cn] = acc[i][j] + bias[cn];
        }
    }
}

// ---------------- batch-axis attention: per (s, head) 64x64 --------------------
__global__ void __launch_bounds__(256) attn_kernel()
{
    int s = blockIdx.x, h = blockIdx.y;
    extern __shared__ float sm_a[];
    float* Qs = sm_a;                    // [64][129] (reused for V)
    float* Ks = sm_a + 64 * 129;
    float* Ss = sm_a + 2 * 64 * 129;     // [64][65]
    int tid = threadIdx.x;

    #pragma unroll
    for (int i = 0; i < 8; i++) {
        int idx4 = tid + 256 * i;        // 2048 float4 per matrix
        int b  = idx4 >> 5;
        int dq = idx4 & 31;
        size_t rbase = (size_t)(b * SS + s) * (3 * E2) + h * HD + dq * 4;
        float4 q = *(const float4*)(g_qkv + rbase);
        float4 k = *(const float4*)(g_qkv + rbase + E2);
        Qs[b*129 + dq*4+0] = q.x; Qs[b*129 + dq*4+1] = q.y;
        Qs[b*129 + dq*4+2] = q.z; Qs[b*129 + dq*4+3] = q.w;
        Ks[b*129 + dq*4+0] = k.x; Ks[b*129 + dq*4+1] = k.y;
        Ks[b*129 + dq*4+2] = k.z; Ks[b*129 + dq*4+3] = k.w;
    }
    __syncthreads();

    const float scale = 0.08838834764831845f;   // 1/sqrt(128)
    #pragma unroll
    for (int e0 = 0; e0 < 16; e0++) {
        int e = tid + 256 * e0;          // 4096 scores
        int i = e >> 6, j = e & 63;
        float acc = 0.f;
        #pragma unroll 4
        for (int k = 0; k < HD; k++) acc += Qs[i*129 + k] * Ks[j*129 + k];
        Ss[i * 65 + j] = acc * scale;
    }
    __syncthreads();

    // V into Qs (Q dead after scores)
    #pragma unroll
    for (int i = 0; i < 8; i++) {
        int idx4 = tid + 256 * i;
        int b  = idx4 >> 5;
        int dq = idx4 & 31;
        size_t rbase = (size_t)(b * SS + s) * (3 * E2) + h * HD + dq * 4 + 2 * E2;
        float4 v = *(const float4*)(g_qkv + rbase);
        Qs[b*129 + dq*4+0] = v.x; Qs[b*129 + dq*4+1] = v.y;
        Qs[b*129 + dq*4+2] = v.z; Qs[b*129 + dq*4+3] = v.w;
    }
    __syncthreads();
    if (tid < 64) {
        int i = tid;
        float m = -1e30f;
        #pragma unroll 4
        for (int j = 0; j < 64; j++) m = fmaxf(m, Ss[i*65 + j]);
        float sum = 0.f;
        #pragma unroll 4
        for (int j = 0; j < 64; j++) {
            float ev = expf(Ss[i*65 + j] - m);
            Ss[i*65 + j] = ev;
            sum += ev;
        }
        float inv = 1.f / sum;
        #pragma unroll 4
        for (int j = 0; j < 64; j++) Ss[i*65 + j] *= inv;
    }
    __syncthreads();

    #pragma unroll
    for (int o0 = 0; o0 < 32; o0++) {
        int idx = tid + 256 * o0;        // 8192 outputs
        int i = idx >> 7, dd = idx & 127;
        float acc = 0.f;
        #pragma unroll 4
        for (int j = 0; j < 64; j++) acc += Ss[i*65 + j] * Qs[j*129 + dd];
        g_att[(size_t)(i * SS + s) * E2 + h * HD + dd] = acc;
    }
}

// ---------------- emissions: em = ao @ w_lin^T + b_lin -------------------------
__global__ void __launch_bounds__(256) em_kernel(
    const float* __restrict__ wl, const float* __restrict__ bl)
{
    __shared__ float ws[LL * E2];
    __shared__ float bs[LL];
    int tid = threadIdx.x;
    for (int i = tid; i < LL * E2; i += 256) ws[i] = wl[i];
    if (tid < LL) bs[tid] = bl[tid];
    __syncthreads();

    int warp = tid >> 5, lane = tid & 31;
    int token = blockIdx.x * 8 + warp;

    const float* arow = g_ao + (size_t)token * E2;
    float acc[LL];
    #pragma unroll
    for (int j = 0; j < LL; j++) acc[j] = 0.f;

    #pragma unroll 4
    for (int it = 0; it < E2 / 32; it++) {
        int dd = lane + 32 * it;
        float a = arow[dd];
        #pragma unroll
        for (int j = 0; j < LL; j++) acc[j] += a * ws[j * E2 + dd];
    }
    #pragma unroll
    for (int j = 0; j < LL; j++) {
        float v = acc[j];
        #pragma unroll
        for (int off = 16; off; off >>= 1)
            v += __shfl_down_sync(0xffffffffu, v, off);
        if (lane == 0) g_em[(size_t)token * LL + j] = v + bs[j];
    }
}

// ---------------- Viterbi decode: one warp per batch (float32 output) ----------
__global__ void __launch_bounds__(32) viterbi_kernel(
    const float* __restrict__ start, const float* __restrict__ endv,
    const float* __restrict__ trans, float* __restrict__ out)
{
    int b = blockIdx.x;
    int j = threadIdx.x;
    __shared__ unsigned char hist[SS * LL];

    const float* em = g_em + (size_t)b * SS * LL;

    float tr[LL];
    if (j < LL) {
        #pragma unroll
        for (int i = 0; i < LL; i++) tr[i] = trans[i * LL + j];
    }
    float score = (j < LL) ? (start[j] + em[j]) : -1e30f;

    for (int t = 1; t < SS; t++) {
        float e = (j < LL) ? em[t * LL + j] : 0.f;
        float best = -1e30f;
        int bi = 0;
        #pragma unroll
        for (int i = 0; i < LL; i++) {
            float si = __shfl_sync(0xffffffffu, score, i);
            float v = si + ((j < LL) ? tr[i] : 0.f);
            if (v > best) { best = v; bi = i; }
        }
        if (j < LL) hist[t * LL + j] = (unsigned char)bi;
        score = best + e;
    }
    if (j < LL) score += endv[j];

    // convergence-safe final argmax (first-max tie-break == jnp.argmax)
    float s = (j < LL) ? score : -3e30f;
    int   idx = j;
    #pragma unroll
    for (int off = 16; off; off >>= 1) {
        float so = __shfl_down_sync(0xffffffffu, s, off);
        int   io = __shfl_down_sync(0xffffffffu, idx, off);
        if (so > s || (so == s && io < idx)) { s = so; idx = io; }
    }
    int last = __shfl_sync(0xffffffffu, idx, 0);

    __syncwarp();
    if (j == 0) {
        out[b * SS + SS - 1] = (float)last;
        int tag = last;
        for (int t = SS - 1; t >= 1; t--) {
            tag = hist[t * LL + tag];
            out[b * SS + t - 1] = (float)tag;
        }
    }
}

// ---------------- launch -------------------------------------------------------
extern "C" void kernel_launch(void* const* d_in, const int* in_sizes, int n_in,
                              void* d_out, int out_size)
{
    // ---- size-based input dispatch (robust to pruned metadata) ----
    const void *p_input=0, *p_embed=0, *p_wihf=0, *p_bf=0, *p_wihb=0, *p_bb=0;
    const void *p_whhf=0, *p_whhb=0, *p_wo=0, *p_wqkv=0, *p_bqkv=0, *p_bo=0;
    const void *p_wlin=0, *p_blin=0, *p_start=0, *p_end=0, *p_trans=0;
    int c32k = 0, c131k = 0, c262k = 0, c1k = 0, c9 = 0;
    for (int i = 0; i < n_in; i++) {
        int sz = in_sizes[i];
        const void* p = d_in[i];
        if      (sz == 252160) p_embed = p;
        else if (sz == 786432) p_wqkv  = p;
        else if (sz == 1536)   p_bqkv  = p;
        else if (sz == 512)    p_bo    = p;
        else if (sz == 4608)   p_wlin  = p;
        else if (sz == 81)     p_trans = p;
        else if (sz == 32768)  { if (c32k == 0) p_input = p; c32k++; }
        else if (sz == 131072) { if (c131k == 0) p_wihf = p; else p_wihb = p; c131k++; }
        else if (sz == 262144) { if (c262k == 0) p_whhf = p; else if (c262k == 1) p_whhb = p; else p_wo = p; c262k++; }
        else if (sz == 1024)   { if (c1k == 0) p_bf = p; else p_bb = p; c1k++; }
        else if (sz == 9)      { if (c9 == 0) p_blin = p; else if (c9 == 1) p_start = p; else p_end = p; c9++; }
    }

    const int*   inp    = (const int*)  p_input;
    const float* embed  = (const float*)p_embed;
    const float* w_ih_f = (const float*)p_wihf;
    const float* w_hh_f = (const float*)p_whhf;
    const float* b_f    = (const float*)p_bf;
    const float* w_ih_b = (const float*)p_wihb;
    const float* w_hh_b = (const float*)p_whhb;
    const float* b_b    = (const float*)p_bb;
    const float* wqkv   = (const float*)p_wqkv;
    const float* bqkv   = (const float*)p_bqkv;
    const float* wo     = (const float*)p_wo;
    const float* bo     = (const float*)p_bo;
    const float* w_lin  = (const float*)p_wlin;
    const float* b_lin  = (const float*)p_blin;
    const float* startv = (const float*)p_start;
    const float* endv   = (const float*)p_end;
    const float* transv = (const float*)p_trans;
    float* out = (float*)d_out;

    cudaFuncSetAttribute(proj_kernel, cudaFuncAttributeMaxDynamicSharedMemorySize, PROJ_SMEM);
    cudaFuncSetAttribute(lstm_kernel, cudaFuncAttributeMaxDynamicSharedMemorySize, LSTM_SMEM);
    cudaFuncSetAttribute(attn_kernel, cudaFuncAttributeMaxDynamicSharedMemorySize, ATTN_SMEM);

    float* g_hall_p; cudaGetSymbolAddress((void**)&g_hall_p, g_hall);
    float* g_qkv_p;  cudaGetSymbolAddress((void**)&g_qkv_p,  g_qkv);
    float* g_att_p;  cudaGetSymbolAddress((void**)&g_att_p,  g_att);
    float* g_ao_p;   cudaGetSymbolAddress((void**)&g_ao_p,   g_ao);

    reset_kernel<<<256, 256>>>();
    proj_kernel<<<dim3(SS, 16), 256, PROJ_SMEM>>>(inp, embed, w_ih_f, b_f, w_ih_b, b_b);
    lstm_kernel<<<128, 256, LSTM_SMEM>>>(w_hh_f, w_hh_b);
    sgemm_bias<<<dim3(12, 256), 256>>>(g_hall_p, wqkv, bqkv, g_qkv_p, NTOK, 3*E2, E2);
    attn_kernel<<<dim3(SS, NHH), 256, ATTN_SMEM>>>();
    sgemm_bias<<<dim3(4, 256), 256>>>(g_att_p, wo, bo, g_ao_p, NTOK, E2, E2);
    em_kernel<<<NTOK/8, 256>>>(w_lin, b_lin);
    viterbi_kernel<<<BB, 32>>>(startv, endv, transv, out);
}